// round 1
// baseline (speedup 1.0000x reference)
#include <cuda_runtime.h>
#include <math.h>

#define B_DIM 4
#define S_DIM 2048
#define T_TOK (B_DIM * S_DIM)   // 8192
#define D_DIM 1024
#define F_DIM 4096
#define E_NUM 8

// ---------------- device scratch (no allocations allowed) ----------------
__device__ int   g_cnti[E_NUM];
__device__ int   g_off[E_NUM];
__device__ int   g_cursor[E_NUM];
__device__ float g_scoresum[E_NUM];
__device__ int   g_eidx[T_TOK];
__device__ float g_wgt[T_TOK];
__device__ int   g_tok[T_TOK];
// GLU activations, grouped by expert: [T_TOK, F_DIM] fp32 = 134 MB
__device__ float g_G[(size_t)T_TOK * F_DIM];

// ---------------- stage 0: zero accumulators ----------------
__global__ void zero_kernel() {
    int i = threadIdx.x;
    if (i < E_NUM) {
        g_cnti[i] = 0;
        g_cursor[i] = 0;
        g_scoresum[i] = 0.0f;
    }
}

// ---------------- stage 1: gating (one warp per token) ----------------
__global__ __launch_bounds__(256) void gate_kernel(const float* __restrict__ x,
                                                   const float* __restrict__ Wg,
                                                   const float* __restrict__ bg) {
    int t = blockIdx.x * 8 + (threadIdx.x >> 5);
    int lane = threadIdx.x & 31;
    if (t >= T_TOK) return;

    float acc[E_NUM];
#pragma unroll
    for (int e = 0; e < E_NUM; e++) acc[e] = 0.0f;

    const float* xp = x + (size_t)t * D_DIM;
    for (int k = lane; k < D_DIM; k += 32) {
        float xv = xp[k];
        const float4 w0 = *(const float4*)(Wg + (size_t)k * E_NUM);
        const float4 w1 = *(const float4*)(Wg + (size_t)k * E_NUM + 4);
        acc[0] += xv * w0.x; acc[1] += xv * w0.y; acc[2] += xv * w0.z; acc[3] += xv * w0.w;
        acc[4] += xv * w1.x; acc[5] += xv * w1.y; acc[6] += xv * w1.z; acc[7] += xv * w1.w;
    }
#pragma unroll
    for (int e = 0; e < E_NUM; e++)
#pragma unroll
        for (int o = 16; o > 0; o >>= 1)
            acc[e] += __shfl_down_sync(0xffffffffu, acc[e], o);

    if (lane == 0) {
        float mx = -1e30f;
#pragma unroll
        for (int e = 0; e < E_NUM; e++) {
            acc[e] += bg[e];
            mx = fmaxf(mx, acc[e]);
        }
        float s = 0.0f, p[E_NUM];
#pragma unroll
        for (int e = 0; e < E_NUM; e++) { p[e] = expf(acc[e] - mx); s += p[e]; }
        float inv = 1.0f / s;
        float best = -1.0f; int bi = 0;
#pragma unroll
        for (int e = 0; e < E_NUM; e++) {
            float pe = p[e] * inv;
            if (pe > best) { best = pe; bi = e; }  // strict > keeps first index on tie
        }
        g_eidx[t] = bi;
        g_wgt[t] = best;
        atomicAdd(&g_scoresum[bi], best);
        atomicAdd(&g_cnti[bi], 1);
    }
}

// ---------------- stage 2: offsets + utilization loss ----------------
__global__ void scan_loss_kernel(float* __restrict__ out, int write_loss) {
    if (threadIdx.x == 0 && blockIdx.x == 0) {
        int off = 0;
        float loss = 0.0f;
#pragma unroll
        for (int e = 0; e < E_NUM; e++) {
            g_off[e] = off;
            off += g_cnti[e];
            float usage = g_scoresum[e] / ((float)g_cnti[e] + 1e-8f);
            float d = usage - 1.0f / (float)E_NUM;
            loss += d * d;
        }
        if (write_loss) out[(size_t)T_TOK * D_DIM] = loss;
    }
}

// ---------------- stage 3: scatter token ids into grouped lists ----------------
__global__ void scatter_kernel() {
    int t = blockIdx.x * blockDim.x + threadIdx.x;
    if (t >= T_TOK) return;
    int e = g_eidx[t];
    int pos = atomicAdd(&g_cursor[e], 1);
    g_tok[g_off[e] + pos] = t;
}

__device__ __forceinline__ float gelu_exact(float v) {
    return 0.5f * v * (1.0f + erff(v * 0.70710678118654752f));
}

// ---------------- stage 4: grouped GEMM1 + fused GLU ----------------
// C[r, n] = sum_k X[tok(r), k] * Wfc[e][k, n]  for n and n+F_DIM, then GLU.
// grid = (F_DIM/64, T_TOK/64, E_NUM), block = 256
__global__ __launch_bounds__(256) void gemm1_kernel(const float* __restrict__ x,
                                                    const float* __restrict__ Wfc,
                                                    const float* __restrict__ bfc) {
    int e = blockIdx.z;
    int cnt = g_cnti[e];
    int row0 = blockIdx.y * 64;
    if (row0 >= cnt) return;
    int col0 = blockIdx.x * 64;

    const float* Bm = Wfc + (size_t)e * D_DIM * (2 * F_DIM);

    __shared__ float As[16][64];
    __shared__ float B1s[16][64];
    __shared__ float B2s[16][64];

    int tid = threadIdx.x;
    // A loader: one float4 along K per thread
    int a_row = tid >> 2;          // 0..63
    int a_k4  = (tid & 3) * 4;     // 0,4,8,12
    int grow  = row0 + a_row;
    const float* aptr = nullptr;
    if (grow < cnt) aptr = x + (size_t)g_tok[g_off[e] + grow] * D_DIM;
    // B loader: one float4 along N per thread (per B tile)
    int b_k = tid >> 4;            // 0..15
    int b_n = (tid & 15) * 4;      // 0..60

    int tx = tid & 15;             // col group
    int ty = tid >> 4;             // row group

    float acc1[4][4], acc2[4][4];
#pragma unroll
    for (int i = 0; i < 4; i++)
#pragma unroll
        for (int j = 0; j < 4; j++) { acc1[i][j] = 0.0f; acc2[i][j] = 0.0f; }

    for (int k0 = 0; k0 < D_DIM; k0 += 16) {
        float4 av = aptr ? *(const float4*)(aptr + k0 + a_k4) : make_float4(0.f, 0.f, 0.f, 0.f);
        As[a_k4 + 0][a_row] = av.x;
        As[a_k4 + 1][a_row] = av.y;
        As[a_k4 + 2][a_row] = av.z;
        As[a_k4 + 3][a_row] = av.w;
        const float* bp = Bm + (size_t)(k0 + b_k) * (2 * F_DIM) + col0 + b_n;
        *(float4*)&B1s[b_k][b_n] = *(const float4*)bp;
        *(float4*)&B2s[b_k][b_n] = *(const float4*)(bp + F_DIM);
        __syncthreads();

#pragma unroll
        for (int kk = 0; kk < 16; kk++) {
            float a[4], b1[4], b2[4];
            *(float4*)a  = *(const float4*)&As[kk][ty * 4];
            *(float4*)b1 = *(const float4*)&B1s[kk][tx * 4];
            *(float4*)b2 = *(const float4*)&B2s[kk][tx * 4];
#pragma unroll
            for (int i = 0; i < 4; i++)
#pragma unroll
                for (int j = 0; j < 4; j++) {
                    acc1[i][j] = fmaf(a[i], b1[j], acc1[i][j]);
                    acc2[i][j] = fmaf(a[i], b2[j], acc2[i][j]);
                }
        }
        __syncthreads();
    }

    int off = g_off[e];
    const float* bias = bfc + (size_t)e * (2 * F_DIM);
#pragma unroll
    for (int i = 0; i < 4; i++) {
        int r = row0 + ty * 4 + i;
        if (r >= cnt) continue;
        size_t gbase = (size_t)(off + r) * F_DIM + col0 + tx * 4;
#pragma unroll
        for (int j = 0; j < 4; j++) {
            int n = col0 + tx * 4 + j;
            float h1 = acc1[i][j] + bias[n];
            float h2 = acc2[i][j] + bias[F_DIM + n];
            g_G[gbase + j] = h1 * gelu_exact(h2);
        }
    }
}

// ---------------- stage 5: grouped GEMM2 + fused scale/scatter ----------------
// out[tok(r), n] = wgt(tok) * (sum_k G[r, k] * Wout[e][k, n] + bout[e][n])
// grid = (D_DIM/64, T_TOK/64, E_NUM), block = 256
__global__ __launch_bounds__(256) void gemm2_kernel(const float* __restrict__ Wout,
                                                    const float* __restrict__ bout,
                                                    float* __restrict__ out) {
    int e = blockIdx.z;
    int cnt = g_cnti[e];
    int row0 = blockIdx.y * 64;
    if (row0 >= cnt) return;
    int col0 = blockIdx.x * 64;

    const float* Bm = Wout + (size_t)e * F_DIM * D_DIM;
    int off = g_off[e];

    __shared__ float As[16][64];
    __shared__ float Bs[16][64];

    int tid = threadIdx.x;
    int a_row = tid >> 2;
    int a_k4  = (tid & 3) * 4;
    int grow  = row0 + a_row;
    const float* aptr = (grow < cnt) ? (g_G + (size_t)(off + grow) * F_DIM) : nullptr;
    int b_k = tid >> 4;
    int b_n = (tid & 15) * 4;

    int tx = tid & 15;
    int ty = tid >> 4;

    float acc[4][4];
#pragma unroll
    for (int i = 0; i < 4; i++)
#pragma unroll
        for (int j = 0; j < 4; j++) acc[i][j] = 0.0f;

    for (int k0 = 0; k0 < F_DIM; k0 += 16) {
        float4 av = aptr ? *(const float4*)(aptr + k0 + a_k4) : make_float4(0.f, 0.f, 0.f, 0.f);
        As[a_k4 + 0][a_row] = av.x;
        As[a_k4 + 1][a_row] = av.y;
        As[a_k4 + 2][a_row] = av.z;
        As[a_k4 + 3][a_row] = av.w;
        *(float4*)&Bs[b_k][b_n] =
            *(const float4*)(Bm + (size_t)(k0 + b_k) * D_DIM + col0 + b_n);
        __syncthreads();

#pragma unroll
        for (int kk = 0; kk < 16; kk++) {
            float a[4], b[4];
            *(float4*)a = *(const float4*)&As[kk][ty * 4];
            *(float4*)b = *(const float4*)&Bs[kk][tx * 4];
#pragma unroll
            for (int i = 0; i < 4; i++)
#pragma unroll
                for (int j = 0; j < 4; j++)
                    acc[i][j] = fmaf(a[i], b[j], acc[i][j]);
        }
        __syncthreads();
    }

    const float* bias = bout + (size_t)e * D_DIM;
#pragma unroll
    for (int i = 0; i < 4; i++) {
        int r = row0 + ty * 4 + i;
        if (r >= cnt) continue;
        int tok = g_tok[off + r];
        float w = g_wgt[tok];
        float* op = out + (size_t)tok * D_DIM + col0 + tx * 4;
#pragma unroll
        for (int j = 0; j < 4; j++) {
            int n = col0 + tx * 4 + j;
            op[j] = w * (acc[i][j] + bias[n]);
        }
    }
}

// ---------------- launch ----------------
extern "C" void kernel_launch(void* const* d_in, const int* in_sizes, int n_in,
                              void* d_out, int out_size) {
    const float* x    = (const float*)d_in[0];
    const float* Wg   = (const float*)d_in[1];
    const float* bg   = (const float*)d_in[2];
    const float* Wfc  = (const float*)d_in[3];
    const float* bfc  = (const float*)d_in[4];
    const float* Wout = (const float*)d_in[5];
    const float* bout = (const float*)d_in[6];
    float* out = (float*)d_out;

    int write_loss = (out_size > T_TOK * D_DIM) ? 1 : 0;

    zero_kernel<<<1, 32>>>();
    gate_kernel<<<T_TOK / 8, 256>>>(x, Wg, bg);
    scan_loss_kernel<<<1, 32>>>(out, write_loss);
    scatter_kernel<<<T_TOK / 256, 256>>>();
    {
        dim3 grid(F_DIM / 64, T_TOK / 64, E_NUM);
        gemm1_kernel<<<grid, 256>>>(x, Wfc, bfc);
    }
    {
        dim3 grid(D_DIM / 64, T_TOK / 64, E_NUM);
        gemm2_kernel<<<grid, 256>>>(Wout, bout, out);
    }
}

// round 3
// speedup vs baseline: 1.0002x; 1.0002x over previous
#include <cuda_runtime.h>
#include <math.h>

#define B_DIM 4
#define S_DIM 2048
#define T_TOK (B_DIM * S_DIM)   // 8192
#define D_DIM 1024
#define F_DIM 4096
#define E_NUM 8

// ---------------- device scratch (no allocations allowed) ----------------
__device__ int   g_cnti[E_NUM];
__device__ int   g_off[E_NUM];
__device__ int   g_cursor[E_NUM];
__device__ float g_scoresum[E_NUM];
__device__ int   g_eidx[T_TOK];
__device__ float g_wgt[T_TOK];
__device__ int   g_tok[T_TOK];
// GLU activations, grouped by expert: [T_TOK, F_DIM] fp32 = 134 MB
__device__ float g_G[(size_t)T_TOK * F_DIM];

// ---------------- stage 0: zero accumulators ----------------
__global__ void zero_kernel() {
    int i = threadIdx.x;
    if (i < E_NUM) {
        g_cnti[i] = 0;
        g_cursor[i] = 0;
        g_scoresum[i] = 0.0f;
    }
}

// ---------------- stage 1: gating (one warp per token) ----------------
__global__ __launch_bounds__(256) void gate_kernel(const float* __restrict__ x,
                                                   const float* __restrict__ Wg,
                                                   const float* __restrict__ bg) {
    int t = blockIdx.x * 8 + (threadIdx.x >> 5);
    int lane = threadIdx.x & 31;
    if (t >= T_TOK) return;

    float acc[E_NUM];
#pragma unroll
    for (int e = 0; e < E_NUM; e++) acc[e] = 0.0f;

    const float* xp = x + (size_t)t * D_DIM;
    for (int k = lane; k < D_DIM; k += 32) {
        float xv = xp[k];
        const float4 w0 = *(const float4*)(Wg + (size_t)k * E_NUM);
        const float4 w1 = *(const float4*)(Wg + (size_t)k * E_NUM + 4);
        acc[0] += xv * w0.x; acc[1] += xv * w0.y; acc[2] += xv * w0.z; acc[3] += xv * w0.w;
        acc[4] += xv * w1.x; acc[5] += xv * w1.y; acc[6] += xv * w1.z; acc[7] += xv * w1.w;
    }
#pragma unroll
    for (int e = 0; e < E_NUM; e++)
#pragma unroll
        for (int o = 16; o > 0; o >>= 1)
            acc[e] += __shfl_down_sync(0xffffffffu, acc[e], o);

    if (lane == 0) {
        float mx = -1e30f;
#pragma unroll
        for (int e = 0; e < E_NUM; e++) {
            acc[e] += bg[e];
            mx = fmaxf(mx, acc[e]);
        }
        float s = 0.0f, p[E_NUM];
#pragma unroll
        for (int e = 0; e < E_NUM; e++) { p[e] = expf(acc[e] - mx); s += p[e]; }
        float inv = 1.0f / s;
        float best = -1.0f; int bi = 0;
#pragma unroll
        for (int e = 0; e < E_NUM; e++) {
            float pe = p[e] * inv;
            if (pe > best) { best = pe; bi = e; }  // strict > keeps first index on tie
        }
        g_eidx[t] = bi;
        g_wgt[t] = best;
        atomicAdd(&g_scoresum[bi], best);
        atomicAdd(&g_cnti[bi], 1);
    }
}

// ---------------- stage 2: offsets + utilization loss ----------------
__global__ void scan_loss_kernel(float* __restrict__ out, int write_loss) {
    if (threadIdx.x == 0 && blockIdx.x == 0) {
        int off = 0;
        float loss = 0.0f;
#pragma unroll
        for (int e = 0; e < E_NUM; e++) {
            g_off[e] = off;
            off += g_cnti[e];
            float usage = g_scoresum[e] / ((float)g_cnti[e] + 1e-8f);
            float d = usage - 1.0f / (float)E_NUM;
            loss += d * d;
        }
        if (write_loss) out[(size_t)T_TOK * D_DIM] = loss;
    }
}

// ---------------- stage 3: scatter token ids into grouped lists ----------------
__global__ void scatter_kernel() {
    int t = blockIdx.x * blockDim.x + threadIdx.x;
    if (t >= T_TOK) return;
    int e = g_eidx[t];
    int pos = atomicAdd(&g_cursor[e], 1);
    g_tok[g_off[e] + pos] = t;
}

__device__ __forceinline__ float gelu_exact(float v) {
    return 0.5f * v * (1.0f + erff(v * 0.70710678118654752f));
}

// ---------------- stage 4: grouped GEMM1 + fused GLU ----------------
// C[r, n] = sum_k X[tok(r), k] * Wfc[e][k, n]  for n and n+F_DIM, then GLU.
// grid = (F_DIM/64, T_TOK/64, E_NUM), block = 256
__global__ __launch_bounds__(256) void gemm1_kernel(const float* __restrict__ x,
                                                    const float* __restrict__ Wfc,
                                                    const float* __restrict__ bfc) {
    int e = blockIdx.z;
    int cnt = g_cnti[e];
    int row0 = blockIdx.y * 64;
    if (row0 >= cnt) return;
    int col0 = blockIdx.x * 64;

    const float* Bm = Wfc + (size_t)e * D_DIM * (2 * F_DIM);

    __shared__ float As[16][64];
    __shared__ float B1s[16][64];
    __shared__ float B2s[16][64];

    int tid = threadIdx.x;
    // A loader: one float4 along K per thread
    int a_row = tid >> 2;          // 0..63
    int a_k4  = (tid & 3) * 4;     // 0,4,8,12
    int grow  = row0 + a_row;
    const float* aptr = nullptr;
    if (grow < cnt) aptr = x + (size_t)g_tok[g_off[e] + grow] * D_DIM;
    // B loader: one float4 along N per thread (per B tile)
    int b_k = tid >> 4;            // 0..15
    int b_n = (tid & 15) * 4;      // 0..60

    int tx = tid & 15;             // col group
    int ty = tid >> 4;             // row group

    float acc1[4][4], acc2[4][4];
#pragma unroll
    for (int i = 0; i < 4; i++)
#pragma unroll
        for (int j = 0; j < 4; j++) { acc1[i][j] = 0.0f; acc2[i][j] = 0.0f; }

    for (int k0 = 0; k0 < D_DIM; k0 += 16) {
        float4 av = aptr ? *(const float4*)(aptr + k0 + a_k4) : make_float4(0.f, 0.f, 0.f, 0.f);
        As[a_k4 + 0][a_row] = av.x;
        As[a_k4 + 1][a_row] = av.y;
        As[a_k4 + 2][a_row] = av.z;
        As[a_k4 + 3][a_row] = av.w;
        const float* bp = Bm + (size_t)(k0 + b_k) * (2 * F_DIM) + col0 + b_n;
        *(float4*)&B1s[b_k][b_n] = *(const float4*)bp;
        *(float4*)&B2s[b_k][b_n] = *(const float4*)(bp + F_DIM);
        __syncthreads();

#pragma unroll
        for (int kk = 0; kk < 16; kk++) {
            float a[4], b1[4], b2[4];
            *(float4*)a  = *(const float4*)&As[kk][ty * 4];
            *(float4*)b1 = *(const float4*)&B1s[kk][tx * 4];
            *(float4*)b2 = *(const float4*)&B2s[kk][tx * 4];
#pragma unroll
            for (int i = 0; i < 4; i++)
#pragma unroll
                for (int j = 0; j < 4; j++) {
                    acc1[i][j] = fmaf(a[i], b1[j], acc1[i][j]);
                    acc2[i][j] = fmaf(a[i], b2[j], acc2[i][j]);
                }
        }
        __syncthreads();
    }

    int off = g_off[e];
    const float* bias = bfc + (size_t)e * (2 * F_DIM);
#pragma unroll
    for (int i = 0; i < 4; i++) {
        int r = row0 + ty * 4 + i;
        if (r >= cnt) continue;
        size_t gbase = (size_t)(off + r) * F_DIM + col0 + tx * 4;
#pragma unroll
        for (int j = 0; j < 4; j++) {
            int n = col0 + tx * 4 + j;
            float h1 = acc1[i][j] + bias[n];
            float h2 = acc2[i][j] + bias[F_DIM + n];
            g_G[gbase + j] = h1 * gelu_exact(h2);
        }
    }
}

// ---------------- stage 5: grouped GEMM2 + fused scale/scatter ----------------
// out[tok(r), n] = wgt(tok) * (sum_k G[r, k] * Wout[e][k, n] + bout[e][n])
// grid = (D_DIM/64, T_TOK/64, E_NUM), block = 256
__global__ __launch_bounds__(256) void gemm2_kernel(const float* __restrict__ Wout,
                                                    const float* __restrict__ bout,
                                                    float* __restrict__ out) {
    int e = blockIdx.z;
    int cnt = g_cnti[e];
    int row0 = blockIdx.y * 64;
    if (row0 >= cnt) return;
    int col0 = blockIdx.x * 64;

    const float* Bm = Wout + (size_t)e * F_DIM * D_DIM;
    int off = g_off[e];

    __shared__ float As[16][64];
    __shared__ float Bs[16][64];

    int tid = threadIdx.x;
    int a_row = tid >> 2;
    int a_k4  = (tid & 3) * 4;
    int grow  = row0 + a_row;
    const float* aptr = (grow < cnt) ? (g_G + (size_t)(off + grow) * F_DIM) : nullptr;
    int b_k = tid >> 4;
    int b_n = (tid & 15) * 4;

    int tx = tid & 15;
    int ty = tid >> 4;

    float acc[4][4];
#pragma unroll
    for (int i = 0; i < 4; i++)
#pragma unroll
        for (int j = 0; j < 4; j++) acc[i][j] = 0.0f;

    for (int k0 = 0; k0 < F_DIM; k0 += 16) {
        float4 av = aptr ? *(const float4*)(aptr + k0 + a_k4) : make_float4(0.f, 0.f, 0.f, 0.f);
        As[a_k4 + 0][a_row] = av.x;
        As[a_k4 + 1][a_row] = av.y;
        As[a_k4 + 2][a_row] = av.z;
        As[a_k4 + 3][a_row] = av.w;
        *(float4*)&Bs[b_k][b_n] =
            *(const float4*)(Bm + (size_t)(k0 + b_k) * D_DIM + col0 + b_n);
        __syncthreads();

#pragma unroll
        for (int kk = 0; kk < 16; kk++) {
            float a[4], b[4];
            *(float4*)a = *(const float4*)&As[kk][ty * 4];
            *(float4*)b = *(const float4*)&Bs[kk][tx * 4];
#pragma unroll
            for (int i = 0; i < 4; i++)
#pragma unroll
                for (int j = 0; j < 4; j++)
                    acc[i][j] = fmaf(a[i], b[j], acc[i][j]);
        }
        __syncthreads();
    }

    const float* bias = bout + (size_t)e * D_DIM;
#pragma unroll
    for (int i = 0; i < 4; i++) {
        int r = row0 + ty * 4 + i;
        if (r >= cnt) continue;
        int tok = g_tok[off + r];
        float w = g_wgt[tok];
        float* op = out + (size_t)tok * D_DIM + col0 + tx * 4;
#pragma unroll
        for (int j = 0; j < 4; j++) {
            int n = col0 + tx * 4 + j;
            op[j] = w * (acc[i][j] + bias[n]);
        }
    }
}

// ---------------- launch ----------------
extern "C" void kernel_launch(void* const* d_in, const int* in_sizes, int n_in,
                              void* d_out, int out_size) {
    const float* x    = (const float*)d_in[0];
    const float* Wg   = (const float*)d_in[1];
    const float* bg   = (const float*)d_in[2];
    const float* Wfc  = (const float*)d_in[3];
    const float* bfc  = (const float*)d_in[4];
    const float* Wout = (const float*)d_in[5];
    const float* bout = (const float*)d_in[6];
    float* out = (float*)d_out;

    int write_loss = (out_size > T_TOK * D_DIM) ? 1 : 0;

    zero_kernel<<<1, 32>>>();
    gate_kernel<<<T_TOK / 8, 256>>>(x, Wg, bg);
    scan_loss_kernel<<<1, 32>>>(out, write_loss);
    scatter_kernel<<<T_TOK / 256, 256>>>();
    {
        dim3 grid(F_DIM / 64, T_TOK / 64, E_NUM);
        gemm1_kernel<<<grid, 256>>>(x, Wfc, bfc);
    }
    {
        dim3 grid(D_DIM / 64, T_TOK / 64, E_NUM);
        gemm2_kernel<<<grid, 256>>>(Wout, bout, out);
    }
}

// round 6
// speedup vs baseline: 3.1666x; 3.1661x over previous
#include <cuda_runtime.h>
#include <math.h>
#include <stdint.h>

#define T_TOK 8192
#define D_DIM 1024
#define F_DIM 4096
#define E_NUM 8

// ---------------- device scratch ----------------
__device__ int   g_cnti[E_NUM];
__device__ int   g_off[E_NUM];
__device__ int   g_cursor[E_NUM];
__device__ float g_scoresum[E_NUM];
__device__ int   g_eidx[T_TOK];
__device__ float g_wgt[T_TOK];
__device__ int   g_tok[T_TOK];
// GLU activations, grouped by expert: [T_TOK, F_DIM] fp32
__device__ float g_G[(size_t)T_TOK * F_DIM];

// ---------------- helpers ----------------
__device__ __forceinline__ uint32_t smem_u32(const void* p) {
    uint32_t a;
    asm("{ .reg .u64 t; cvta.to.shared.u64 t, %1; cvt.u32.u64 %0, t; }" : "=r"(a) : "l"(p));
    return a;
}
__device__ __forceinline__ uint32_t cvt_tf32(float f) {
    uint32_t u; asm("cvt.rna.tf32.f32 %0, %1;" : "=r"(u) : "f"(f));
    return u;
}
__device__ __forceinline__ void cp16(uint32_t d, const void* s) {
    asm volatile("cp.async.cg.shared.global [%0], [%1], 16;" :: "r"(d), "l"(s));
}
__device__ __forceinline__ void cp_commit() { asm volatile("cp.async.commit_group;"); }
template <int N> __device__ __forceinline__ void cp_wait() {
    asm volatile("cp.async.wait_group %0;" :: "n"(N));
}
__device__ __forceinline__ void mma8(float* c, const uint32_t* a, const uint32_t* b) {
    asm volatile(
        "mma.sync.aligned.m16n8k8.row.col.f32.tf32.tf32.f32 "
        "{%0,%1,%2,%3}, {%4,%5,%6,%7}, {%8,%9}, {%0,%1,%2,%3};"
        : "+f"(c[0]), "+f"(c[1]), "+f"(c[2]), "+f"(c[3])
        : "r"(a[0]), "r"(a[1]), "r"(a[2]), "r"(a[3]), "r"(b[0]), "r"(b[1]));
}
__device__ __forceinline__ float gelu_exact(float v) {
    return 0.5f * v * (1.0f + erff(v * 0.70710678118654752f));
}

// ---------------- stage 0: zero ----------------
__global__ void zero_kernel() {
    int i = threadIdx.x;
    if (i < E_NUM) { g_cnti[i] = 0; g_cursor[i] = 0; g_scoresum[i] = 0.0f; }
}

// ---------------- stage 1: gating (fp32 exact) ----------------
__global__ __launch_bounds__(256) void gate_kernel(const float* __restrict__ x,
                                                   const float* __restrict__ Wg,
                                                   const float* __restrict__ bg) {
    int t = blockIdx.x * 8 + (threadIdx.x >> 5);
    int lane = threadIdx.x & 31;
    if (t >= T_TOK) return;
    float acc[E_NUM];
#pragma unroll
    for (int e = 0; e < E_NUM; e++) acc[e] = 0.0f;
    const float* xp = x + (size_t)t * D_DIM;
    for (int k = lane; k < D_DIM; k += 32) {
        float xv = xp[k];
        const float4 w0 = *(const float4*)(Wg + (size_t)k * E_NUM);
        const float4 w1 = *(const float4*)(Wg + (size_t)k * E_NUM + 4);
        acc[0] += xv * w0.x; acc[1] += xv * w0.y; acc[2] += xv * w0.z; acc[3] += xv * w0.w;
        acc[4] += xv * w1.x; acc[5] += xv * w1.y; acc[6] += xv * w1.z; acc[7] += xv * w1.w;
    }
#pragma unroll
    for (int e = 0; e < E_NUM; e++)
#pragma unroll
        for (int o = 16; o > 0; o >>= 1)
            acc[e] += __shfl_down_sync(0xffffffffu, acc[e], o);
    if (lane == 0) {
        float mx = -1e30f;
#pragma unroll
        for (int e = 0; e < E_NUM; e++) { acc[e] += bg[e]; mx = fmaxf(mx, acc[e]); }
        float s = 0.0f, p[E_NUM];
#pragma unroll
        for (int e = 0; e < E_NUM; e++) { p[e] = expf(acc[e] - mx); s += p[e]; }
        float inv = 1.0f / s;
        float best = -1.0f; int bi = 0;
#pragma unroll
        for (int e = 0; e < E_NUM; e++) {
            float pe = p[e] * inv;
            if (pe > best) { best = pe; bi = e; }
        }
        g_eidx[t] = bi;
        g_wgt[t] = best;
        atomicAdd(&g_scoresum[bi], best);
        atomicAdd(&g_cnti[bi], 1);
    }
}

// ---------------- stage 2: offsets + loss ----------------
__global__ void scan_loss_kernel(float* __restrict__ out, int write_loss) {
    if (threadIdx.x == 0 && blockIdx.x == 0) {
        int off = 0;
        float loss = 0.0f;
#pragma unroll
        for (int e = 0; e < E_NUM; e++) {
            g_off[e] = off;
            off += g_cnti[e];
            float usage = g_scoresum[e] / ((float)g_cnti[e] + 1e-8f);
            float d = usage - 1.0f / (float)E_NUM;
            loss += d * d;
        }
        if (write_loss) out[(size_t)T_TOK * D_DIM] = loss;
    }
}

// ---------------- stage 3: scatter ----------------
__global__ void scatter_kernel() {
    int t = blockIdx.x * blockDim.x + threadIdx.x;
    if (t >= T_TOK) return;
    int e = g_eidx[t];
    int pos = atomicAdd(&g_cursor[e], 1);
    g_tok[g_off[e] + pos] = t;
}

// ================= GEMM1: tokens[128] x (64 + 64 GLU cols), K=1024 =================
// SMEM per stage: A 128x16 pad 20 floats (10240B), B1/B2 16x64 pad 72 floats (4608B each)
#define G1_A_BYTES 10240
#define G1_B_BYTES 4608
#define G1_STAGE (G1_A_BYTES + 2 * G1_B_BYTES)   // 19456
#define G1_SMEM (4 * G1_STAGE)                   // 77824

__global__ __launch_bounds__(256) void gemm1_kernel(const float* __restrict__ x,
                                                    const float* __restrict__ Wfc,
                                                    const float* __restrict__ bfc) {
    extern __shared__ __align__(128) char smem_raw[];
    uint32_t sb = smem_u32(smem_raw);
    int e = blockIdx.z;
    int cnt = g_cnti[e];
    int row0 = blockIdx.y * 128;
    if (row0 >= cnt) return;
    int col0 = blockIdx.x * 64;
    int off = g_off[e];
    int tid = threadIdx.x, wid = tid >> 5, lane = tid & 31;
    int g = lane >> 2, t4 = lane & 3;
    int wm = wid & 1, wn = wid >> 1;   // 2 x 4 warp grid; warp tile 64 x 16

    // ---- loader setup ----
    // A: ids tid, tid+256 -> row = id>>2 (0..127), c = id&3 (16B chunk)
    int a_r0 = tid >> 2,       a_c0 = tid & 3;
    int a_r1 = (tid + 256) >> 2, a_c1 = (tid + 256) & 3;
    int gi0 = off + row0 + a_r0; if (gi0 > T_TOK - 1) gi0 = T_TOK - 1;
    int gi1 = off + row0 + a_r1; if (gi1 > T_TOK - 1) gi1 = T_TOK - 1;
    const float* asrc0 = x + (size_t)g_tok[gi0] * D_DIM + a_c0 * 4;
    const float* asrc1 = x + (size_t)g_tok[gi1] * D_DIM + a_c1 * 4;
    uint32_t adst0 = (uint32_t)(a_r0 * 80 + a_c0 * 16);
    uint32_t adst1 = (uint32_t)(a_r1 * 80 + a_c1 * 16);
    // B: kk = tid>>4 (0..15), n4 = tid&15
    int b_kk = tid >> 4, b_n4 = tid & 15;
    const float* bbase = Wfc + (size_t)e * D_DIM * (2 * F_DIM) +
                         (size_t)b_kk * (2 * F_DIM) + col0 + b_n4 * 4;
    uint32_t bdst = (uint32_t)(b_kk * 288 + b_n4 * 16);

#define G1_LOAD(k0, st)                                                       \
    {                                                                         \
        uint32_t base = sb + (uint32_t)(st) * G1_STAGE;                       \
        cp16(base + adst0, asrc0 + (k0));                                     \
        cp16(base + adst1, asrc1 + (k0));                                     \
        const float* bp = bbase + (size_t)(k0) * (2 * F_DIM);                 \
        cp16(base + G1_A_BYTES + bdst, bp);                                   \
        cp16(base + G1_A_BYTES + G1_B_BYTES + bdst, bp + F_DIM);              \
        cp_commit();                                                          \
    }

    float c1r[4][2][4], c2r[4][2][4];
#pragma unroll
    for (int mi = 0; mi < 4; mi++)
#pragma unroll
        for (int ni = 0; ni < 2; ni++)
#pragma unroll
            for (int q = 0; q < 4; q++) { c1r[mi][ni][q] = 0.0f; c2r[mi][ni][q] = 0.0f; }

    const int NCH = D_DIM / 16;  // 64
    G1_LOAD(0, 0); G1_LOAD(16, 1); G1_LOAD(32, 2);

    for (int c = 0; c < NCH; c++) {
        int st = c & 3;
        cp_wait<2>();
        __syncthreads();
        int nc = c + 3;
        if (nc < NCH) { G1_LOAD(nc * 16, nc & 3); } else { cp_commit(); }

        const float* As = (const float*)(smem_raw + st * G1_STAGE);
        const float* B1 = (const float*)(smem_raw + st * G1_STAGE + G1_A_BYTES);
        const float* B2 = (const float*)(smem_raw + st * G1_STAGE + G1_A_BYTES + G1_B_BYTES);
#pragma unroll
        for (int k8 = 0; k8 < 16; k8 += 8) {
            uint32_t af[4][4], bf1[2][2], bf2[2][2];
#pragma unroll
            for (int mi = 0; mi < 4; mi++) {
                const float* ap = As + (wm * 64 + mi * 16 + g) * 20 + k8 + t4;
                af[mi][0] = cvt_tf32(ap[0]);
                af[mi][1] = cvt_tf32(ap[8 * 20]);
                af[mi][2] = cvt_tf32(ap[4]);
                af[mi][3] = cvt_tf32(ap[8 * 20 + 4]);
            }
#pragma unroll
            for (int ni = 0; ni < 2; ni++) {
                int n = wn * 16 + ni * 8 + g;
                const float* bp1 = B1 + (k8 + t4) * 72 + n;
                bf1[ni][0] = cvt_tf32(bp1[0]);
                bf1[ni][1] = cvt_tf32(bp1[4 * 72]);
                const float* bp2 = B2 + (k8 + t4) * 72 + n;
                bf2[ni][0] = cvt_tf32(bp2[0]);
                bf2[ni][1] = cvt_tf32(bp2[4 * 72]);
            }
#pragma unroll
            for (int mi = 0; mi < 4; mi++)
#pragma unroll
                for (int ni = 0; ni < 2; ni++) {
                    mma8(c1r[mi][ni], af[mi], bf1[ni]);
                    mma8(c2r[mi][ni], af[mi], bf2[ni]);
                }
        }
    }
#undef G1_LOAD

    // epilogue: bias + GLU -> g_G (grouped rows)
    const float* bias = bfc + (size_t)e * (2 * F_DIM);
#pragma unroll
    for (int mi = 0; mi < 4; mi++) {
        int rl = wm * 64 + mi * 16 + g;
#pragma unroll
        for (int ni = 0; ni < 2; ni++) {
            int n = col0 + wn * 16 + ni * 8 + 2 * t4;
            float b1a = bias[n], b1b = bias[n + 1];
            float b2a = bias[F_DIM + n], b2b = bias[F_DIM + n + 1];
            if (row0 + rl < cnt) {
                float h1 = c1r[mi][ni][0] + b1a, h2 = c2r[mi][ni][0] + b2a;
                float u1 = c1r[mi][ni][1] + b1b, u2 = c2r[mi][ni][1] + b2b;
                float2 v = make_float2(h1 * gelu_exact(h2), u1 * gelu_exact(u2));
                *(float2*)(g_G + (size_t)(off + row0 + rl) * F_DIM + n) = v;
            }
            if (row0 + rl + 8 < cnt) {
                float h1 = c1r[mi][ni][2] + b1a, h2 = c2r[mi][ni][2] + b2a;
                float u1 = c1r[mi][ni][3] + b1b, u2 = c2r[mi][ni][3] + b2b;
                float2 v = make_float2(h1 * gelu_exact(h2), u1 * gelu_exact(u2));
                *(float2*)(g_G + (size_t)(off + row0 + rl + 8) * F_DIM + n) = v;
            }
        }
    }
}

// ================= GEMM2: rows[128] x 64 D cols, K=4096 =================
#define G2_A_BYTES 10240
#define G2_B_BYTES 4608
#define G2_STAGE (G2_A_BYTES + G2_B_BYTES)   // 14848
#define G2_SMEM (4 * G2_STAGE)               // 59392

__global__ __launch_bounds__(256) void gemm2_kernel(const float* __restrict__ Wout,
                                                    const float* __restrict__ bout,
                                                    float* __restrict__ out) {
    extern __shared__ __align__(128) char smem_raw[];
    uint32_t sb = smem_u32(smem_raw);
    int e = blockIdx.z;
    int cnt = g_cnti[e];
    int row0 = blockIdx.y * 128;
    if (row0 >= cnt) return;
    int col0 = blockIdx.x * 64;
    int off = g_off[e];
    int tid = threadIdx.x, wid = tid >> 5, lane = tid & 31;
    int g = lane >> 2, t4 = lane & 3;
    int wm = wid & 1, wn = wid >> 1;

    int a_r0 = tid >> 2,         a_c0 = tid & 3;
    int a_r1 = (tid + 256) >> 2, a_c1 = (tid + 256) & 3;
    int gi0 = off + row0 + a_r0; if (gi0 > T_TOK - 1) gi0 = T_TOK - 1;
    int gi1 = off + row0 + a_r1; if (gi1 > T_TOK - 1) gi1 = T_TOK - 1;
    const float* asrc0 = g_G + (size_t)gi0 * F_DIM + a_c0 * 4;
    const float* asrc1 = g_G + (size_t)gi1 * F_DIM + a_c1 * 4;
    uint32_t adst0 = (uint32_t)(a_r0 * 80 + a_c0 * 16);
    uint32_t adst1 = (uint32_t)(a_r1 * 80 + a_c1 * 16);
    int b_kk = tid >> 4, b_n4 = tid & 15;
    const float* bbase = Wout + (size_t)e * F_DIM * D_DIM +
                         (size_t)b_kk * D_DIM + col0 + b_n4 * 4;
    uint32_t bdst = (uint32_t)(b_kk * 288 + b_n4 * 16);

#define G2_LOAD(k0, st)                                       \
    {                                                         \
        uint32_t base = sb + (uint32_t)(st) * G2_STAGE;       \
        cp16(base + adst0, asrc0 + (k0));                     \
        cp16(base + adst1, asrc1 + (k0));                     \
        cp16(base + G2_A_BYTES + bdst, bbase + (size_t)(k0) * D_DIM); \
        cp_commit();                                          \
    }

    float cr[4][2][4];
#pragma unroll
    for (int mi = 0; mi < 4; mi++)
#pragma unroll
        for (int ni = 0; ni < 2; ni++)
#pragma unroll
            for (int q = 0; q < 4; q++) cr[mi][ni][q] = 0.0f;

    const int NCH = F_DIM / 16;  // 256
    G2_LOAD(0, 0); G2_LOAD(16, 1); G2_LOAD(32, 2);

    for (int c = 0; c < NCH; c++) {
        int st = c & 3;
        cp_wait<2>();
        __syncthreads();
        int nc = c + 3;
        if (nc < NCH) { G2_LOAD(nc * 16, nc & 3); } else { cp_commit(); }

        const float* As = (const float*)(smem_raw + st * G2_STAGE);
        const float* Bs = (const float*)(smem_raw + st * G2_STAGE + G2_A_BYTES);
#pragma unroll
        for (int k8 = 0; k8 < 16; k8 += 8) {
            uint32_t af[4][4], bf[2][2];
#pragma unroll
            for (int mi = 0; mi < 4; mi++) {
                const float* ap = As + (wm * 64 + mi * 16 + g) * 20 + k8 + t4;
                af[mi][0] = cvt_tf32(ap[0]);
                af[mi][1] = cvt_tf32(ap[8 * 20]);
                af[mi][2] = cvt_tf32(ap[4]);
                af[mi][3] = cvt_tf32(ap[8 * 20 + 4]);
            }
#pragma unroll
            for (int ni = 0; ni < 2; ni++) {
                int n = wn * 16 + ni * 8 + g;
                const float* bp = Bs + (k8 + t4) * 72 + n;
                bf[ni][0] = cvt_tf32(bp[0]);
                bf[ni][1] = cvt_tf32(bp[4 * 72]);
            }
#pragma unroll
            for (int mi = 0; mi < 4; mi++)
#pragma unroll
                for (int ni = 0; ni < 2; ni++)
                    mma8(cr[mi][ni], af[mi], bf[ni]);
        }
    }
#undef G2_LOAD

    const float* bias = bout + (size_t)e * D_DIM;
#pragma unroll
    for (int mi = 0; mi < 4; mi++) {
        int rl = wm * 64 + mi * 16 + g;
#pragma unroll
        for (int ni = 0; ni < 2; ni++) {
            int n = col0 + wn * 16 + ni * 8 + 2 * t4;
            float ba = bias[n], bb = bias[n + 1];
            if (row0 + rl < cnt) {
                int tok = g_tok[off + row0 + rl];
                float w = g_wgt[tok];
                float2 v = make_float2(w * (cr[mi][ni][0] + ba),
                                       w * (cr[mi][ni][1] + bb));
                *(float2*)(out + (size_t)tok * D_DIM + n) = v;
            }
            if (row0 + rl + 8 < cnt) {
                int tok = g_tok[off + row0 + rl + 8];
                float w = g_wgt[tok];
                float2 v = make_float2(w * (cr[mi][ni][2] + ba),
                                       w * (cr[mi][ni][3] + bb));
                *(float2*)(out + (size_t)tok * D_DIM + n) = v;
            }
        }
    }
}

// ---------------- launch ----------------
extern "C" void kernel_launch(void* const* d_in, const int* in_sizes, int n_in,
                              void* d_out, int out_size) {
    const float* x    = (const float*)d_in[0];
    const float* Wg   = (const float*)d_in[1];
    const float* bg   = (const float*)d_in[2];
    const float* Wfc  = (const float*)d_in[3];
    const float* bfc  = (const float*)d_in[4];
    const float* Wout = (const float*)d_in[5];
    const float* bout = (const float*)d_in[6];
    float* out = (float*)d_out;
    int write_loss = (out_size > T_TOK * D_DIM) ? 1 : 0;

    cudaFuncSetAttribute(gemm1_kernel, cudaFuncAttributeMaxDynamicSharedMemorySize, G1_SMEM);
    cudaFuncSetAttribute(gemm2_kernel, cudaFuncAttributeMaxDynamicSharedMemorySize, G2_SMEM);

    zero_kernel<<<1, 32>>>();
    gate_kernel<<<T_TOK / 8, 256>>>(x, Wg, bg);
    scan_loss_kernel<<<1, 32>>>(out, write_loss);
    scatter_kernel<<<T_TOK / 256, 256>>>();
    {
        dim3 grid(F_DIM / 64, T_TOK / 128, E_NUM);
        gemm1_kernel<<<grid, 256, G1_SMEM>>>(x, Wfc, bfc);
    }
    {
        dim3 grid(D_DIM / 64, T_TOK / 128, E_NUM);
        gemm2_kernel<<<grid, 256, G2_SMEM>>>(Wout, bout, out);
    }
}